// round 3
// baseline (speedup 1.0000x reference)
#include <cuda_runtime.h>
#include <cuda_fp16.h>
#include <cuda_bf16.h>
#include <cstdint>

// y[16384,4096] = x[16384,4096] @ w[4096,4096]^T + b
#define M_TOT 16384
#define N_TOT 4096
#define K_TOT 4096
#define G_BLK 32
#define NB_BLOCKS ((N_TOT * K_TOT) / G_BLK)   // 524288

#define BLK_M 128
#define BLK_N 128
#define BLK_K 64                  // halves; one 128B smem row per tile-row
#define K_ITERS (K_TOT / BLK_K)   // 64
#define STAGES 4
#define GEMM_THREADS 256          // 8 warps: 4 along M x 2 along N, warp tile 32x64

// Scratch (allocation-free rule: __device__ globals)
__device__ __half g_xf16[(size_t)M_TOT * K_TOT];   // 128 MB
__device__ __half g_wf16[(size_t)N_TOT * K_TOT];   // 32 MB
__device__ int g_scale_mode;   // 0=fp16, 1=bf16, 2=fp32
__device__ int g_mask_mode;    // 0=u8, 1=i32, 2=f32

// ---------------- helpers ----------------
__device__ __forceinline__ uint32_t smem_u32(const void* p) {
    uint32_t a;
    asm("{ .reg .u64 t; cvta.to.shared.u64 t, %1; cvt.u32.u64 %0, t; }" : "=r"(a) : "l"(p));
    return a;
}
__device__ __forceinline__ void cp16(uint32_t dst, const void* src) {
    asm volatile("cp.async.cg.shared.global [%0], [%1], 16;" :: "r"(dst), "l"(src) : "memory");
}
__device__ __forceinline__ void cp_commit() {
    asm volatile("cp.async.commit_group;" ::: "memory");
}
template <int N>
__device__ __forceinline__ void cp_wait() {
    asm volatile("cp.async.wait_group %0;" :: "n"(N) : "memory");
}
__device__ __forceinline__ void ldmatrix_x4(uint32_t* r, uint32_t addr) {
    asm volatile("ldmatrix.sync.aligned.m8n8.x4.shared.b16 {%0,%1,%2,%3}, [%4];"
                 : "=r"(r[0]), "=r"(r[1]), "=r"(r[2]), "=r"(r[3]) : "r"(addr));
}
__device__ __forceinline__ void mma16816(float* c, const uint32_t* a, uint32_t b0, uint32_t b1) {
    asm volatile(
        "mma.sync.aligned.m16n8k16.row.col.f32.f16.f16.f32 "
        "{%0,%1,%2,%3}, {%4,%5,%6,%7}, {%8,%9}, {%0,%1,%2,%3};"
        : "+f"(c[0]), "+f"(c[1]), "+f"(c[2]), "+f"(c[3])
        : "r"(a[0]), "r"(a[1]), "r"(a[2]), "r"(a[3]), "r"(b0), "r"(b1));
}
__device__ __forceinline__ uint32_t sw128(uint32_t off) {   // SW128 swizzle
    return off ^ ((off >> 3) & 0x70);
}

// ---------------- Kernel 0: detect input encodings ----------------
__global__ void detect_kernel(const void* scale_raw, const void* mask_raw) {
    if (threadIdx.x != 0 || blockIdx.x != 0) return;

    // ---- scale: expected values uniform(0, 0.02), mean ~0.01 ----
    {
        const __half* h = (const __half*)scale_raw;
        const __nv_bfloat16* bf = (const __nv_bfloat16*)scale_raw;
        const float* f = (const float*)scale_raw;
        int mode = 2;
        // fp16 view
        {
            bool ok = true; float s = 0.f, mx = 0.f;
            for (int i = 0; i < 256; i++) {
                float v = fabsf(__half2float(h[i]));
                if (!(v == v) || v > 1e30f) { ok = false; break; }
                s += v; if (v > mx) mx = v;
            }
            if (ok && mx < 0.05f && s > 256 * 0.005f && s < 256 * 0.015f) mode = 0;
        }
        if (mode == 2) {   // bf16 view
            bool ok = true; float s = 0.f, mx = 0.f;
            for (int i = 0; i < 256; i++) {
                float v = fabsf(__bfloat162float(bf[i]));
                if (!(v == v) || v > 1e30f) { ok = false; break; }
                s += v; if (v > mx) mx = v;
            }
            if (ok && mx < 0.05f && s > 256 * 0.005f && s < 256 * 0.015f) mode = 1;
        }
        (void)f;
        g_scale_mode = mode;
    }

    // ---- mask: expected values {0,1}, ~50% ones ----
    {
        const float* f = (const float*)mask_raw;
        const int* ii = (const int*)mask_raw;
        int mode = 0;
        // f32 view: all exactly 0.0 or 1.0, at least one 1.0
        {
            bool ok = true; int ones = 0;
            for (int i = 0; i < 256; i++) {
                float v = f[i];
                if (v == 1.0f) ones++;
                else if (v != 0.0f) { ok = false; break; }
            }
            if (ok && ones > 0) mode = 2;
        }
        if (mode == 0) {   // i32 view: all 0/1, at least one 1
            bool ok = true; int ones = 0;
            for (int i = 0; i < 256; i++) {
                int v = ii[i];
                if (v == 1) ones++;
                else if (v != 0) { ok = false; break; }
            }
            if (ok && ones > 0) mode = 1;
        }
        g_mask_mode = mode;   // default 0 = u8
    }
}

// ---------------- Kernel 1: x fp32 -> fp16 ----------------
__global__ void convert_x_kernel(const float* __restrict__ x) {
    size_t i = ((size_t)blockIdx.x * blockDim.x + threadIdx.x) * 8;
    float4 a = *reinterpret_cast<const float4*>(x + i);
    float4 b = *reinterpret_cast<const float4*>(x + i + 4);
    __half2 h0 = __floats2half2_rn(a.x, a.y);
    __half2 h1 = __floats2half2_rn(a.z, a.w);
    __half2 h2 = __floats2half2_rn(b.x, b.y);
    __half2 h3 = __floats2half2_rn(b.z, b.w);
    uint4 o;
    o.x = *reinterpret_cast<uint32_t*>(&h0);
    o.y = *reinterpret_cast<uint32_t*>(&h1);
    o.z = *reinterpret_cast<uint32_t*>(&h2);
    o.w = *reinterpret_cast<uint32_t*>(&h3);
    *reinterpret_cast<uint4*>(g_xf16 + i) = o;
}

// ---------------- Kernel 2: int4 block dequant -> fp16 [OUT][IN] ----------------
// packed: [NB, 16] int32; each int32 holds one byte value 0..255 = two uint4 (lo,hi interleaved)
__global__ void dequant_w_kernel(const int* __restrict__ packed,
                                 const void* __restrict__ scale,
                                 const void* __restrict__ mask) {
    int nb = blockIdx.x * blockDim.x + threadIdx.x;   // one quant block per thread

    float sc;
    int smode = g_scale_mode;
    if (smode == 0)      sc = __half2float(((const __half*)scale)[nb]);
    else if (smode == 1) sc = __bfloat162float(((const __nv_bfloat16*)scale)[nb]);
    else                 sc = ((const float*)scale)[nb];

    bool mk;
    int mmode = g_mask_mode;
    if (mmode == 0)      mk = ((const unsigned char*)mask)[nb] != 0;
    else if (mmode == 1) mk = ((const int*)mask)[nb] != 0;
    else                 mk = ((const float*)mask)[nb] != 0.0f;

    float se = sc * (mk ? 1.0f : 0.5f);
    const int4* p = reinterpret_cast<const int4*>(packed) + (size_t)nb * 4;
    uint4* dst = reinterpret_cast<uint4*>(g_wf16 + (size_t)nb * G_BLK);
#pragma unroll
    for (int g = 0; g < 4; g++) {
        int4 v = p[g];
        int vv[4] = {v.x, v.y, v.z, v.w};
        uint32_t res[4];
#pragma unroll
        for (int j = 0; j < 4; j++) {
            int b = vv[j];
            float lo = (float)((b & 0xF) - 8) * se;
            float hi = (float)(((b >> 4) & 0xF) - 8) * se;
            __half2 h = __floats2half2_rn(lo, hi);
            res[j] = *reinterpret_cast<uint32_t*>(&h);
        }
        dst[g] = make_uint4(res[0], res[1], res[2], res[3]);
    }
}

// ---------------- Kernel 3: HMMA fp16 GEMM 128x128x64, 4-stage cp.async ----------------
#define STAGE_BYTES (BLK_M * 128 + BLK_N * 128)       // 16K A + 16K B = 32K
#define SMEM_TOTAL  (STAGES * STAGE_BYTES)            // 128K

__global__ void __launch_bounds__(GEMM_THREADS, 1)
gemm_kernel(const float* __restrict__ bias, float* __restrict__ out) {
    extern __shared__ __align__(1024) char smem[];
    const uint32_t sb = smem_u32(smem);
    const int tid = threadIdx.x;
    const int wid = tid >> 5;
    const int lid = tid & 31;

    // CTA swizzle: groups of 8 m-tiles x all 32 n-tiles -> B stays L2-resident
    const int bid = blockIdx.x;
    const int group = bid >> 8;           // 256 CTAs per group
    const int rem = bid & 255;
    const int mt = (group << 3) + (rem & 7);
    const int nt = rem >> 3;
    const int m_base = mt * BLK_M;
    const int n_base = nt * BLK_N;

    // producer addressing: each thread copies 4 A rows + 4 B rows (16B chunk each)
    const int ch = tid & 7;               // 16B chunk within 128B row
    const int row0 = tid >> 3;            // 0..31
    const __half* aCol = g_xf16 + (size_t)m_base * K_TOT + (size_t)ch * 8;
    const __half* bCol = g_wf16 + (size_t)n_base * K_TOT + (size_t)ch * 8;

    auto issue_stage = [&](int it) {
        const int s = it & (STAGES - 1);
        const uint32_t stA = sb + s * STAGE_BYTES;
        const uint32_t stB = stA + BLK_M * 128;
        const __half* aSrc = aCol + (size_t)it * BLK_K;
        const __half* bSrc = bCol + (size_t)it * BLK_K;
#pragma unroll
        for (int r = 0; r < 4; r++) {
            int row = row0 + (r << 5);
            uint32_t off = row * 128 + ch * 16;
            cp16(stA + sw128(off), aSrc + (size_t)row * K_TOT);
        }
#pragma unroll
        for (int r = 0; r < 4; r++) {
            int row = row0 + (r << 5);
            uint32_t off = row * 128 + ch * 16;
            cp16(stB + sw128(off), bSrc + (size_t)row * K_TOT);
        }
        cp_commit();
    };

    // prologue: fill STAGES-1 stages
#pragma unroll
    for (int it = 0; it < STAGES - 1; it++) issue_stage(it);

    // warp tiling: 4 warps along M, 2 along N; warp tile 32x64
    const int wm = wid >> 1;              // 0..3
    const int wn = wid & 1;               // 0..1
    float acc[2][8][4];                   // [m16][n8][frag]
#pragma unroll
    for (int i = 0; i < 2; i++)
#pragma unroll
        for (int j = 0; j < 8; j++)
#pragma unroll
            for (int k = 0; k < 4; k++) acc[i][j][k] = 0.f;

    // ldmatrix lane addressing: row = lid%16, colHalf = (lid/16)*8
    const int lrow = lid & 15;
    const int lcol = (lid >> 4) << 3;

#pragma unroll 1
    for (int it = 0; it < K_ITERS; it++) {
        cp_wait<STAGES - 2>();
        __syncthreads();
        const int s = it & (STAGES - 1);
        const uint32_t stA = sb + s * STAGE_BYTES;
        const uint32_t stB = stA + BLK_M * 128;

#pragma unroll
        for (int ks = 0; ks < 4; ks++) {          // 4 x k16 per BLK_K=64
            const int kh = ks * 16 + lcol;        // half offset in row
            uint32_t a[2][4], b[4][4];
#pragma unroll
            for (int mi = 0; mi < 2; mi++) {
                int row = wm * 32 + mi * 16 + lrow;
                ldmatrix_x4(a[mi], stA + sw128(row * 128 + kh * 2));
            }
#pragma unroll
            for (int ni = 0; ni < 4; ni++) {
                int row = wn * 64 + ni * 16 + lrow;
                ldmatrix_x4(b[ni], stB + sw128(row * 128 + kh * 2));
            }
#pragma unroll
            for (int mi = 0; mi < 2; mi++)
#pragma unroll
                for (int ni = 0; ni < 4; ni++) {
                    // b[ni]: {n0-7 k0-7, n8-15 k0-7, n0-7 k8-15, n8-15 k8-15}
                    mma16816(acc[mi][ni * 2 + 0], a[mi], b[ni][0], b[ni][2]);
                    mma16816(acc[mi][ni * 2 + 1], a[mi], b[ni][1], b[ni][3]);
                }
        }
        __syncthreads();
        if (it + STAGES - 1 < K_ITERS) issue_stage(it + STAGES - 1);
    }

    // ---------------- epilogue: fused bias, fp32 out ----------------
    const int qid = lid >> 2;             // 0..7 (row within 8)
    const int qtid = lid & 3;             // col pair
#pragma unroll
    for (int mi = 0; mi < 2; mi++) {
#pragma unroll
        for (int ni = 0; ni < 8; ni++) {
            int col = n_base + wn * 64 + ni * 8 + qtid * 2;
            float2 bv = *reinterpret_cast<const float2*>(bias + col);
            int r0 = m_base + wm * 32 + mi * 16 + qid;
            float2 o0 = make_float2(acc[mi][ni][0] + bv.x, acc[mi][ni][1] + bv.y);
            float2 o1 = make_float2(acc[mi][ni][2] + bv.x, acc[mi][ni][3] + bv.y);
            *reinterpret_cast<float2*>(out + (size_t)r0 * N_TOT + col) = o0;
            *reinterpret_cast<float2*>(out + (size_t)(r0 + 8) * N_TOT + col) = o1;
        }
    }
}

// ---------------- host ----------------
extern "C" void kernel_launch(void* const* d_in, const int* in_sizes, int n_in,
                              void* d_out, int out_size) {
    (void)in_sizes; (void)n_in; (void)out_size;
    const float* x          = (const float*)d_in[0];
    const int* wpacked      = (const int*)d_in[1];
    const void* wscale      = d_in[2];
    const void* wm          = d_in[3];
    const float* bias       = (const float*)d_in[4];
    float* out              = (float*)d_out;

    cudaFuncSetAttribute(gemm_kernel, cudaFuncAttributeMaxDynamicSharedMemorySize, SMEM_TOTAL);

    detect_kernel<<<1, 1>>>(wscale, wm);
    convert_x_kernel<<<(size_t)M_TOT * K_TOT / (8 * 256), 256>>>(x);
    dequant_w_kernel<<<NB_BLOCKS / 256, 256>>>(wpacked, wscale, wm);
    gemm_kernel<<<(M_TOT / BLK_M) * (N_TOT / BLK_N), GEMM_THREADS, SMEM_TOTAL>>>(bias, out);
}

// round 4
// speedup vs baseline: 1.0189x; 1.0189x over previous
#include <cuda_runtime.h>
#include <cuda_fp16.h>
#include <cuda_bf16.h>
#include <cstdint>

// y[16384,4096] = x[16384,4096] @ w[4096,4096]^T + b
#define M_TOT 16384
#define N_TOT 4096
#define K_TOT 4096
#define G_BLK 32
#define NB_BLOCKS ((N_TOT * K_TOT) / G_BLK)   // 524288

#define BLK_M 128
#define BLK_N 256
#define BLK_K 64                  // halves; one 128B smem row per tile-row
#define K_ITERS (K_TOT / BLK_K)   // 64
#define STAGES 4
#define GEMM_THREADS 256          // 8 warps: 2 along M x 4 along N, warp tile 64x64

// Scratch (allocation-free rule: __device__ globals)
__device__ __half g_xf16[(size_t)M_TOT * K_TOT];   // 128 MB
__device__ __half g_wf16[(size_t)N_TOT * K_TOT];   // 32 MB
__device__ int g_scale_mode;   // 0=fp16, 1=bf16, 2=fp32
__device__ int g_mask_mode;    // 0=u8, 1=i32, 2=f32

// ---------------- helpers ----------------
__device__ __forceinline__ uint32_t smem_u32(const void* p) {
    uint32_t a;
    asm("{ .reg .u64 t; cvta.to.shared.u64 t, %1; cvt.u32.u64 %0, t; }" : "=r"(a) : "l"(p));
    return a;
}
__device__ __forceinline__ void cp16(uint32_t dst, const void* src) {
    asm volatile("cp.async.cg.shared.global [%0], [%1], 16;" :: "r"(dst), "l"(src) : "memory");
}
__device__ __forceinline__ void cp_commit() {
    asm volatile("cp.async.commit_group;" ::: "memory");
}
template <int N>
__device__ __forceinline__ void cp_wait() {
    asm volatile("cp.async.wait_group %0;" :: "n"(N) : "memory");
}
__device__ __forceinline__ void ldmatrix_x4(uint32_t* r, uint32_t addr) {
    asm volatile("ldmatrix.sync.aligned.m8n8.x4.shared.b16 {%0,%1,%2,%3}, [%4];"
                 : "=r"(r[0]), "=r"(r[1]), "=r"(r[2]), "=r"(r[3]) : "r"(addr));
}
__device__ __forceinline__ void mma16816(float* c, const uint32_t* a, uint32_t b0, uint32_t b1) {
    asm volatile(
        "mma.sync.aligned.m16n8k16.row.col.f32.f16.f16.f32 "
        "{%0,%1,%2,%3}, {%4,%5,%6,%7}, {%8,%9}, {%0,%1,%2,%3};"
        : "+f"(c[0]), "+f"(c[1]), "+f"(c[2]), "+f"(c[3])
        : "r"(a[0]), "r"(a[1]), "r"(a[2]), "r"(a[3]), "r"(b0), "r"(b1));
}
__device__ __forceinline__ uint32_t sw128(uint32_t off) {   // SW128 swizzle
    return off ^ ((off >> 3) & 0x70);
}

// ---------------- Kernel 0: detect input encodings (unchanged from R3, it works) ----
__global__ void detect_kernel(const void* scale_raw, const void* mask_raw) {
    if (threadIdx.x != 0 || blockIdx.x != 0) return;
    {
        const __half* h = (const __half*)scale_raw;
        const __nv_bfloat16* bf = (const __nv_bfloat16*)scale_raw;
        int mode = 2;
        {
            bool ok = true; float s = 0.f, mx = 0.f;
            for (int i = 0; i < 256; i++) {
                float v = fabsf(__half2float(h[i]));
                if (!(v == v) || v > 1e30f) { ok = false; break; }
                s += v; if (v > mx) mx = v;
            }
            if (ok && mx < 0.05f && s > 256 * 0.005f && s < 256 * 0.015f) mode = 0;
        }
        if (mode == 2) {
            bool ok = true; float s = 0.f, mx = 0.f;
            for (int i = 0; i < 256; i++) {
                float v = fabsf(__bfloat162float(bf[i]));
                if (!(v == v) || v > 1e30f) { ok = false; break; }
                s += v; if (v > mx) mx = v;
            }
            if (ok && mx < 0.05f && s > 256 * 0.005f && s < 256 * 0.015f) mode = 1;
        }
        g_scale_mode = mode;
    }
    {
        const float* f = (const float*)mask_raw;
        const int* ii = (const int*)mask_raw;
        int mode = 0;
        {
            bool ok = true; int ones = 0;
            for (int i = 0; i < 256; i++) {
                float v = f[i];
                if (v == 1.0f) ones++;
                else if (v != 0.0f) { ok = false; break; }
            }
            if (ok && ones > 0) mode = 2;
        }
        if (mode == 0) {
            bool ok = true; int ones = 0;
            for (int i = 0; i < 256; i++) {
                int v = ii[i];
                if (v == 1) ones++;
                else if (v != 0) { ok = false; break; }
            }
            if (ok && ones > 0) mode = 1;
        }
        g_mask_mode = mode;
    }
}

// ---------------- Kernel 1: x fp32 -> fp16 ----------------
__global__ void convert_x_kernel(const float* __restrict__ x) {
    size_t i = ((size_t)blockIdx.x * blockDim.x + threadIdx.x) * 8;
    float4 a = *reinterpret_cast<const float4*>(x + i);
    float4 b = *reinterpret_cast<const float4*>(x + i + 4);
    __half2 h0 = __floats2half2_rn(a.x, a.y);
    __half2 h1 = __floats2half2_rn(a.z, a.w);
    __half2 h2 = __floats2half2_rn(b.x, b.y);
    __half2 h3 = __floats2half2_rn(b.z, b.w);
    uint4 o;
    o.x = *reinterpret_cast<uint32_t*>(&h0);
    o.y = *reinterpret_cast<uint32_t*>(&h1);
    o.z = *reinterpret_cast<uint32_t*>(&h2);
    o.w = *reinterpret_cast<uint32_t*>(&h3);
    *reinterpret_cast<uint4*>(g_xf16 + i) = o;
}

// ---------------- Kernel 2: int4 block dequant -> fp16 [OUT][IN] ----------------
__global__ void dequant_w_kernel(const int* __restrict__ packed,
                                 const void* __restrict__ scale,
                                 const void* __restrict__ mask) {
    int nb = blockIdx.x * blockDim.x + threadIdx.x;

    float sc;
    int smode = g_scale_mode;
    if (smode == 0)      sc = __half2float(((const __half*)scale)[nb]);
    else if (smode == 1) sc = __bfloat162float(((const __nv_bfloat16*)scale)[nb]);
    else                 sc = ((const float*)scale)[nb];

    bool mk;
    int mmode = g_mask_mode;
    if (mmode == 0)      mk = ((const unsigned char*)mask)[nb] != 0;
    else if (mmode == 1) mk = ((const int*)mask)[nb] != 0;
    else                 mk = ((const float*)mask)[nb] != 0.0f;

    float se = sc * (mk ? 1.0f : 0.5f);
    const int4* p = reinterpret_cast<const int4*>(packed) + (size_t)nb * 4;
    uint4* dst = reinterpret_cast<uint4*>(g_wf16 + (size_t)nb * G_BLK);
#pragma unroll
    for (int g = 0; g < 4; g++) {
        int4 v = p[g];
        int vv[4] = {v.x, v.y, v.z, v.w};
        uint32_t res[4];
#pragma unroll
        for (int j = 0; j < 4; j++) {
            int b = vv[j];
            float lo = (float)((b & 0xF) - 8) * se;
            float hi = (float)(((b >> 4) & 0xF) - 8) * se;
            __half2 h = __floats2half2_rn(lo, hi);
            res[j] = *reinterpret_cast<uint32_t*>(&h);
        }
        dst[g] = make_uint4(res[0], res[1], res[2], res[3]);
    }
}

// ---------------- Kernel 3: HMMA fp16 GEMM 128x256x64, 4-stage cp.async ----------------
#define STAGE_BYTES (BLK_M * 128 + BLK_N * 128)       // 16K A + 32K B = 48K
#define SMEM_TOTAL  (STAGES * STAGE_BYTES)            // 192K

__global__ void __launch_bounds__(GEMM_THREADS, 1)
gemm_kernel(const float* __restrict__ bias, float* __restrict__ out) {
    extern __shared__ __align__(1024) char smem[];
    const uint32_t sb = smem_u32(smem);
    const int tid = threadIdx.x;
    const int wid = tid >> 5;
    const int lid = tid & 31;

    // CTA swizzle: groups of 8 m-tiles x all 16 n-tiles (128 CTAs ~ one wave)
    const int bid = blockIdx.x;
    const int group = bid >> 7;
    const int rem = bid & 127;
    const int mt = (group << 3) + (rem & 7);
    const int nt = rem >> 3;                  // 0..15
    const int m_base = mt * BLK_M;
    const int n_base = nt * BLK_N;

    // producer addressing: 16B chunks; A: 4 rows/thread, B: 8 rows/thread
    const int ch = tid & 7;
    const int row0 = tid >> 3;                // 0..31
    const __half* aCol = g_xf16 + (size_t)m_base * K_TOT + (size_t)ch * 8;
    const __half* bCol = g_wf16 + (size_t)n_base * K_TOT + (size_t)ch * 8;

    auto issue_stage = [&](int it) {
        const int s = it & (STAGES - 1);
        const uint32_t stA = sb + s * STAGE_BYTES;
        const uint32_t stB = stA + BLK_M * 128;
        const __half* aSrc = aCol + (size_t)it * BLK_K;
        const __half* bSrc = bCol + (size_t)it * BLK_K;
#pragma unroll
        for (int r = 0; r < 4; r++) {
            int row = row0 + (r << 5);
            uint32_t off = row * 128 + ch * 16;
            cp16(stA + sw128(off), aSrc + (size_t)row * K_TOT);
        }
#pragma unroll
        for (int r = 0; r < 8; r++) {
            int row = row0 + (r << 5);
            uint32_t off = row * 128 + ch * 16;
            cp16(stB + sw128(off), bSrc + (size_t)row * K_TOT);
        }
        cp_commit();
    };

#pragma unroll
    for (int it = 0; it < STAGES - 1; it++) issue_stage(it);

    // warp tiling: 2 warps along M x 4 along N; warp tile 64x64
    const int wm = wid & 1;
    const int wn = wid >> 1;                  // 0..3
    float acc[4][8][4];                       // [m16][n8][frag]
#pragma unroll
    for (int i = 0; i < 4; i++)
#pragma unroll
        for (int j = 0; j < 8; j++)
#pragma unroll
            for (int k = 0; k < 4; k++) acc[i][j][k] = 0.f;

    const int lrow = lid & 15;
    const int lcol = (lid >> 4) << 3;

#pragma unroll 1
    for (int it = 0; it < K_ITERS; it++) {
        cp_wait<STAGES - 2>();
        __syncthreads();
        // issue next stage into slot (it-1)%S; ordered vs last iter's reads by the sync
        if (it + STAGES - 1 < K_ITERS) issue_stage(it + STAGES - 1);

        const int s = it & (STAGES - 1);
        const uint32_t stA = sb + s * STAGE_BYTES;
        const uint32_t stB = stA + BLK_M * 128;

#pragma unroll
        for (int ks = 0; ks < 4; ks++) {          // 4 x k16 per BLK_K=64
            const int kh = ks * 16 + lcol;
            uint32_t a[4][4], b[4][4];
#pragma unroll
            for (int mi = 0; mi < 4; mi++) {
                int row = wm * 64 + mi * 16 + lrow;
                ldmatrix_x4(a[mi], stA + sw128(row * 128 + kh * 2));
            }
#pragma unroll
            for (int ni = 0; ni < 4; ni++) {
                int row = wn * 64 + ni * 16 + lrow;
                ldmatrix_x4(b[ni], stB + sw128(row * 128 + kh * 2));
            }
#pragma unroll
            for (int mi = 0; mi < 4; mi++)
#pragma unroll
                for (int ni = 0; ni < 4; ni++) {
                    mma16816(acc[mi][ni * 2 + 0], a[mi], b[ni][0], b[ni][2]);
                    mma16816(acc[mi][ni * 2 + 1], a[mi], b[ni][1], b[ni][3]);
                }
        }
    }

    // ---------------- epilogue: fused bias, fp32 out ----------------
    const int qid = lid >> 2;
    const int qtid = lid & 3;
#pragma unroll
    for (int mi = 0; mi < 4; mi++) {
#pragma unroll
        for (int ni = 0; ni < 8; ni++) {
            int col = n_base + wn * 64 + ni * 8 + qtid * 2;
            float2 bv = *reinterpret_cast<const float2*>(bias + col);
            int r0 = m_base + wm * 64 + mi * 16 + qid;
            float2 o0 = make_float2(acc[mi][ni][0] + bv.x, acc[mi][ni][1] + bv.y);
            float2 o1 = make_float2(acc[mi][ni][2] + bv.x, acc[mi][ni][3] + bv.y);
            *reinterpret_cast<float2*>(out + (size_t)r0 * N_TOT + col) = o0;
            *reinterpret_cast<float2*>(out + (size_t)(r0 + 8) * N_TOT + col) = o1;
        }
    }
}

// ---------------- host ----------------
extern "C" void kernel_launch(void* const* d_in, const int* in_sizes, int n_in,
                              void* d_out, int out_size) {
    (void)in_sizes; (void)n_in; (void)out_size;
    const float* x          = (const float*)d_in[0];
    const int* wpacked      = (const int*)d_in[1];
    const void* wscale      = d_in[2];
    const void* wm          = d_in[3];
    const float* bias       = (const float*)d_in[4];
    float* out              = (float*)d_out;

    cudaFuncSetAttribute(gemm_kernel, cudaFuncAttributeMaxDynamicSharedMemorySize, SMEM_TOTAL);

    detect_kernel<<<1, 1>>>(wscale, wm);
    convert_x_kernel<<<(size_t)M_TOT * K_TOT / (8 * 256), 256>>>(x);
    dequant_w_kernel<<<NB_BLOCKS / 256, 256>>>(wpacked, wscale, wm);
    gemm_kernel<<<(M_TOT / BLK_M) * (N_TOT / BLK_N), GEMM_THREADS, SMEM_TOTAL>>>(bias, out);
}

// round 5
// speedup vs baseline: 1.0958x; 1.0754x over previous
#include <cuda_runtime.h>
#include <cuda_fp16.h>
#include <cuda_bf16.h>
#include <cstdint>

// y[16384,4096] = x[16384,4096] @ w[4096,4096]^T + b
#define M_TOT 16384
#define N_TOT 4096
#define K_TOT 4096
#define G_BLK 32
#define NB_BLOCKS ((N_TOT * K_TOT) / G_BLK)   // 524288

#define BLK_M 128
#define BLK_N 256
#define BLK_K 64                  // halves; one 128B smem row per tile-row
#define K_ITERS (K_TOT / BLK_K)   // 64
#define STAGES 4
#define GEMM_THREADS 512          // 16 warps: 4 along M x 4 along N, warp tile 32x64

// Scratch (allocation-free rule: __device__ globals)
__device__ __half g_xf16[(size_t)M_TOT * K_TOT];   // 128 MB
__device__ __half g_wf16[(size_t)N_TOT * K_TOT];   // 32 MB
__device__ int g_scale_mode;   // 0=fp16, 1=bf16, 2=fp32
__device__ int g_mask_mode;    // 0=u8, 1=i32, 2=f32

// ---------------- helpers ----------------
__device__ __forceinline__ uint32_t smem_u32(const void* p) {
    uint32_t a;
    asm("{ .reg .u64 t; cvta.to.shared.u64 t, %1; cvt.u32.u64 %0, t; }" : "=r"(a) : "l"(p));
    return a;
}
__device__ __forceinline__ void cp16(uint32_t dst, const void* src) {
    asm volatile("cp.async.cg.shared.global [%0], [%1], 16;" :: "r"(dst), "l"(src) : "memory");
}
__device__ __forceinline__ void cp_commit() {
    asm volatile("cp.async.commit_group;" ::: "memory");
}
template <int N>
__device__ __forceinline__ void cp_wait() {
    asm volatile("cp.async.wait_group %0;" :: "n"(N) : "memory");
}
__device__ __forceinline__ void ldmatrix_x4(uint32_t* r, uint32_t addr) {
    asm volatile("ldmatrix.sync.aligned.m8n8.x4.shared.b16 {%0,%1,%2,%3}, [%4];"
                 : "=r"(r[0]), "=r"(r[1]), "=r"(r[2]), "=r"(r[3]) : "r"(addr));
}
__device__ __forceinline__ void mma16816(float* c, const uint32_t* a, uint32_t b0, uint32_t b1) {
    asm volatile(
        "mma.sync.aligned.m16n8k16.row.col.f32.f16.f16.f32 "
        "{%0,%1,%2,%3}, {%4,%5,%6,%7}, {%8,%9}, {%0,%1,%2,%3};"
        : "+f"(c[0]), "+f"(c[1]), "+f"(c[2]), "+f"(c[3])
        : "r"(a[0]), "r"(a[1]), "r"(a[2]), "r"(a[3]), "r"(b0), "r"(b1));
}
__device__ __forceinline__ uint32_t sw128(uint32_t off) {   // SW128 swizzle
    return off ^ ((off >> 3) & 0x70);
}

// ---------------- Kernel 0: detect input encodings ----------------
__global__ void detect_kernel(const void* scale_raw, const void* mask_raw) {
    if (threadIdx.x != 0 || blockIdx.x != 0) return;
    {
        const __half* h = (const __half*)scale_raw;
        const __nv_bfloat16* bf = (const __nv_bfloat16*)scale_raw;
        int mode = 2;
        {
            bool ok = true; float s = 0.f, mx = 0.f;
            for (int i = 0; i < 256; i++) {
                float v = fabsf(__half2float(h[i]));
                if (!(v == v) || v > 1e30f) { ok = false; break; }
                s += v; if (v > mx) mx = v;
            }
            if (ok && mx < 0.05f && s > 256 * 0.005f && s < 256 * 0.015f) mode = 0;
        }
        if (mode == 2) {
            bool ok = true; float s = 0.f, mx = 0.f;
            for (int i = 0; i < 256; i++) {
                float v = fabsf(__bfloat162float(bf[i]));
                if (!(v == v) || v > 1e30f) { ok = false; break; }
                s += v; if (v > mx) mx = v;
            }
            if (ok && mx < 0.05f && s > 256 * 0.005f && s < 256 * 0.015f) mode = 1;
        }
        g_scale_mode = mode;
    }
    {
        const float* f = (const float*)mask_raw;
        const int* ii = (const int*)mask_raw;
        int mode = 0;
        {
            bool ok = true; int ones = 0;
            for (int i = 0; i < 256; i++) {
                float v = f[i];
                if (v == 1.0f) ones++;
                else if (v != 0.0f) { ok = false; break; }
            }
            if (ok && ones > 0) mode = 2;
        }
        if (mode == 0) {
            bool ok = true; int ones = 0;
            for (int i = 0; i < 256; i++) {
                int v = ii[i];
                if (v == 1) ones++;
                else if (v != 0) { ok = false; break; }
            }
            if (ok && ones > 0) mode = 1;
        }
        g_mask_mode = mode;
    }
}

// ---------------- Kernel 1: x fp32 -> fp16 ----------------
__global__ void convert_x_kernel(const float* __restrict__ x) {
    size_t i = ((size_t)blockIdx.x * blockDim.x + threadIdx.x) * 8;
    float4 a = *reinterpret_cast<const float4*>(x + i);
    float4 b = *reinterpret_cast<const float4*>(x + i + 4);
    __half2 h0 = __floats2half2_rn(a.x, a.y);
    __half2 h1 = __floats2half2_rn(a.z, a.w);
    __half2 h2 = __floats2half2_rn(b.x, b.y);
    __half2 h3 = __floats2half2_rn(b.z, b.w);
    uint4 o;
    o.x = *reinterpret_cast<uint32_t*>(&h0);
    o.y = *reinterpret_cast<uint32_t*>(&h1);
    o.z = *reinterpret_cast<uint32_t*>(&h2);
    o.w = *reinterpret_cast<uint32_t*>(&h3);
    *reinterpret_cast<uint4*>(g_xf16 + i) = o;
}

// ---------------- Kernel 2: int4 block dequant -> fp16 [OUT][IN] ----------------
__global__ void dequant_w_kernel(const int* __restrict__ packed,
                                 const void* __restrict__ scale,
                                 const void* __restrict__ mask) {
    int nb = blockIdx.x * blockDim.x + threadIdx.x;

    float sc;
    int smode = g_scale_mode;
    if (smode == 0)      sc = __half2float(((const __half*)scale)[nb]);
    else if (smode == 1) sc = __bfloat162float(((const __nv_bfloat16*)scale)[nb]);
    else                 sc = ((const float*)scale)[nb];

    bool mk;
    int mmode = g_mask_mode;
    if (mmode == 0)      mk = ((const unsigned char*)mask)[nb] != 0;
    else if (mmode == 1) mk = ((const int*)mask)[nb] != 0;
    else                 mk = ((const float*)mask)[nb] != 0.0f;

    float se = sc * (mk ? 1.0f : 0.5f);
    const int4* p = reinterpret_cast<const int4*>(packed) + (size_t)nb * 4;
    uint4* dst = reinterpret_cast<uint4*>(g_wf16 + (size_t)nb * G_BLK);
#pragma unroll
    for (int g = 0; g < 4; g++) {
        int4 v = p[g];
        int vv[4] = {v.x, v.y, v.z, v.w};
        uint32_t res[4];
#pragma unroll
        for (int j = 0; j < 4; j++) {
            int b = vv[j];
            float lo = (float)((b & 0xF) - 8) * se;
            float hi = (float)(((b >> 4) & 0xF) - 8) * se;
            __half2 h = __floats2half2_rn(lo, hi);
            res[j] = *reinterpret_cast<uint32_t*>(&h);
        }
        dst[g] = make_uint4(res[0], res[1], res[2], res[3]);
    }
}

// ---------------- Kernel 3: HMMA fp16 GEMM 128x256x64, 512 threads ----------------
#define STAGE_BYTES (BLK_M * 128 + BLK_N * 128)       // 16K A + 32K B = 48K
#define SMEM_TOTAL  (STAGES * STAGE_BYTES)            // 192K

__global__ void __launch_bounds__(GEMM_THREADS, 1)
gemm_kernel(const float* __restrict__ bias, float* __restrict__ out) {
    extern __shared__ __align__(1024) char smem[];
    const uint32_t sb = smem_u32(smem);
    const int tid = threadIdx.x;
    const int wid = tid >> 5;
    const int lid = tid & 31;

    // CTA swizzle: groups of 8 m-tiles x all 16 n-tiles (128 CTAs ~ one wave)
    const int bid = blockIdx.x;
    const int group = bid >> 7;
    const int rem = bid & 127;
    const int mt = (group << 3) + (rem & 7);
    const int nt = rem >> 3;                  // 0..15
    const int m_base = mt * BLK_M;
    const int n_base = nt * BLK_N;

    // producer addressing: 16B chunks; 512 threads: A 2 rows/thread, B 4 rows/thread
    const int ch = tid & 7;
    const int row0 = tid >> 3;                // 0..63
    const __half* aCol = g_xf16 + (size_t)m_base * K_TOT + (size_t)ch * 8;
    const __half* bCol = g_wf16 + (size_t)n_base * K_TOT + (size_t)ch * 8;

    auto issue_stage = [&](int it) {
        const int s = it & (STAGES - 1);
        const uint32_t stA = sb + s * STAGE_BYTES;
        const uint32_t stB = stA + BLK_M * 128;
        const __half* aSrc = aCol + (size_t)it * BLK_K;
        const __half* bSrc = bCol + (size_t)it * BLK_K;
#pragma unroll
        for (int r = 0; r < 2; r++) {             // A: 128 rows
            int row = row0 + (r << 6);
            uint32_t off = row * 128 + ch * 16;
            cp16(stA + sw128(off), aSrc + (size_t)row * K_TOT);
        }
#pragma unroll
        for (int r = 0; r < 4; r++) {             // B: 256 rows
            int row = row0 + (r << 6);
            uint32_t off = row * 128 + ch * 16;
            cp16(stB + sw128(off), bSrc + (size_t)row * K_TOT);
        }
        cp_commit();
    };

#pragma unroll
    for (int it = 0; it < STAGES - 1; it++) issue_stage(it);

    // warp tiling: 4 warps along M x 4 along N; warp tile 32x64
    const int wm = wid & 3;
    const int wn = wid >> 2;                  // 0..3
    float acc[2][8][4];                       // [m16][n8][frag]
#pragma unroll
    for (int i = 0; i < 2; i++)
#pragma unroll
        for (int j = 0; j < 8; j++)
#pragma unroll
            for (int k = 0; k < 4; k++) acc[i][j][k] = 0.f;

    const int lrow = lid & 15;
    const int lcol = (lid >> 4) << 3;

#pragma unroll 1
    for (int it = 0; it < K_ITERS; it++) {
        cp_wait<STAGES - 2>();
        __syncthreads();
        // issue next stage into slot (it-1)%S; ordered vs last iter's reads by the sync
        if (it + STAGES - 1 < K_ITERS) issue_stage(it + STAGES - 1);

        const int s = it & (STAGES - 1);
        const uint32_t stA = sb + s * STAGE_BYTES;
        const uint32_t stB = stA + BLK_M * 128;

#pragma unroll
        for (int ks = 0; ks < 4; ks++) {          // 4 x k16 per BLK_K=64
            const int kh = ks * 16 + lcol;
            uint32_t a[2][4], b[4][4];
#pragma unroll
            for (int mi = 0; mi < 2; mi++) {
                int row = wm * 32 + mi * 16 + lrow;
                ldmatrix_x4(a[mi], stA + sw128(row * 128 + kh * 2));
            }
#pragma unroll
            for (int ni = 0; ni < 4; ni++) {
                int row = wn * 64 + ni * 16 + lrow;
                ldmatrix_x4(b[ni], stB + sw128(row * 128 + kh * 2));
            }
#pragma unroll
            for (int mi = 0; mi < 2; mi++)
#pragma unroll
                for (int ni = 0; ni < 4; ni++) {
                    mma16816(acc[mi][ni * 2 + 0], a[mi], b[ni][0], b[ni][2]);
                    mma16816(acc[mi][ni * 2 + 1], a[mi], b[ni][1], b[ni][3]);
                }
        }
    }

    // ---------------- epilogue: fused bias, fp32 out ----------------
    const int qid = lid >> 2;
    const int qtid = lid & 3;
#pragma unroll
    for (int mi = 0; mi < 2; mi++) {
#pragma unroll
        for (int ni = 0; ni < 8; ni++) {
            int col = n_base + wn * 64 + ni * 8 + qtid * 2;
            float2 bv = *reinterpret_cast<const float2*>(bias + col);
            int r0 = m_base + wm * 32 + mi * 16 + qid;
            float2 o0 = make_float2(acc[mi][ni][0] + bv.x, acc[mi][ni][1] + bv.y);
            float2 o1 = make_float2(acc[mi][ni][2] + bv.x, acc[mi][ni][3] + bv.y);
            *reinterpret_cast<float2*>(out + (size_t)r0 * N_TOT + col) = o0;
            *reinterpret_cast<float2*>(out + (size_t)(r0 + 8) * N_TOT + col) = o1;
        }
    }
}

// ---------------- host ----------------
extern "C" void kernel_launch(void* const* d_in, const int* in_sizes, int n_in,
                              void* d_out, int out_size) {
    (void)in_sizes; (void)n_in; (void)out_size;
    const float* x          = (const float*)d_in[0];
    const int* wpacked      = (const int*)d_in[1];
    const void* wscale      = d_in[2];
    const void* wm          = d_in[3];
    const float* bias       = (const float*)d_in[4];
    float* out              = (float*)d_out;

    cudaFuncSetAttribute(gemm_kernel, cudaFuncAttributeMaxDynamicSharedMemorySize, SMEM_TOTAL);

    detect_kernel<<<1, 1>>>(wscale, wm);
    convert_x_kernel<<<(size_t)M_TOT * K_TOT / (8 * 256), 256>>>(x);
    dequant_w_kernel<<<NB_BLOCKS / 256, 256>>>(wpacked, wscale, wm);
    gemm_kernel<<<(M_TOT / BLK_M) * (N_TOT / BLK_N), GEMM_THREADS, SMEM_TOTAL>>>(bias, out);
}

// round 6
// speedup vs baseline: 1.1716x; 1.0692x over previous
#include <cuda_runtime.h>
#include <cuda_fp16.h>
#include <cuda_bf16.h>
#include <cstdint>

// y[16384,4096] = x[16384,4096] @ w[4096,4096]^T + b
#define M_TOT 16384
#define N_TOT 4096
#define K_TOT 4096
#define G_BLK 32
#define NB_BLOCKS ((N_TOT * K_TOT) / G_BLK)   // 524288

#define BLK_M 128
#define BLK_N 128
#define BLK_K 64                  // halves; one 128B smem row per tile-row
#define K_ITERS (K_TOT / BLK_K)   // 64
#define STAGES 3
#define GEMM_THREADS 256          // 8 warps: 4 along M x 2 along N, warp tile 32x64

// Scratch (allocation-free rule: __device__ globals)
__device__ __half g_xf16[(size_t)M_TOT * K_TOT];   // 128 MB
__device__ __half g_wf16[(size_t)N_TOT * K_TOT];   // 32 MB
__device__ int g_scale_mode;   // 0=fp16, 1=bf16, 2=fp32
__device__ int g_mask_mode;    // 0=u8, 1=i32, 2=f32

// ---------------- helpers ----------------
__device__ __forceinline__ uint32_t smem_u32(const void* p) {
    uint32_t a;
    asm("{ .reg .u64 t; cvta.to.shared.u64 t, %1; cvt.u32.u64 %0, t; }" : "=r"(a) : "l"(p));
    return a;
}
__device__ __forceinline__ void cp16(uint32_t dst, const void* src) {
    asm volatile("cp.async.cg.shared.global [%0], [%1], 16;" :: "r"(dst), "l"(src) : "memory");
}
__device__ __forceinline__ void cp_commit() {
    asm volatile("cp.async.commit_group;" ::: "memory");
}
template <int N>
__device__ __forceinline__ void cp_wait() {
    asm volatile("cp.async.wait_group %0;" :: "n"(N) : "memory");
}
__device__ __forceinline__ void ldmatrix_x4(uint32_t* r, uint32_t addr) {
    asm volatile("ldmatrix.sync.aligned.m8n8.x4.shared.b16 {%0,%1,%2,%3}, [%4];"
                 : "=r"(r[0]), "=r"(r[1]), "=r"(r[2]), "=r"(r[3]) : "r"(addr));
}
__device__ __forceinline__ void mma16816(float* c, const uint32_t* a, uint32_t b0, uint32_t b1) {
    asm volatile(
        "mma.sync.aligned.m16n8k16.row.col.f32.f16.f16.f32 "
        "{%0,%1,%2,%3}, {%4,%5,%6,%7}, {%8,%9}, {%0,%1,%2,%3};"
        : "+f"(c[0]), "+f"(c[1]), "+f"(c[2]), "+f"(c[3])
        : "r"(a[0]), "r"(a[1]), "r"(a[2]), "r"(a[3]), "r"(b0), "r"(b1));
}
__device__ __forceinline__ uint32_t sw128(uint32_t off) {   // SW128 swizzle
    return off ^ ((off >> 3) & 0x70);
}

// ---------------- Kernel 0: detect input encodings ----------------
__global__ void detect_kernel(const void* scale_raw, const void* mask_raw) {
    if (threadIdx.x != 0 || blockIdx.x != 0) return;
    {
        const __half* h = (const __half*)scale_raw;
        const __nv_bfloat16* bf = (const __nv_bfloat16*)scale_raw;
        int mode = 2;
        {
            bool ok = true; float s = 0.f, mx = 0.f;
            for (int i = 0; i < 256; i++) {
                float v = fabsf(__half2float(h[i]));
                if (!(v == v) || v > 1e30f) { ok = false; break; }
                s += v; if (v > mx) mx = v;
            }
            if (ok && mx < 0.05f && s > 256 * 0.005f && s < 256 * 0.015f) mode = 0;
        }
        if (mode == 2) {
            bool ok = true; float s = 0.f, mx = 0.f;
            for (int i = 0; i < 256; i++) {
                float v = fabsf(__bfloat162float(bf[i]));
                if (!(v == v) || v > 1e30f) { ok = false; break; }
                s += v; if (v > mx) mx = v;
            }
            if (ok && mx < 0.05f && s > 256 * 0.005f && s < 256 * 0.015f) mode = 1;
        }
        g_scale_mode = mode;
    }
    {
        const float* f = (const float*)mask_raw;
        const int* ii = (const int*)mask_raw;
        int mode = 0;
        {
            bool ok = true; int ones = 0;
            for (int i = 0; i < 256; i++) {
                float v = f[i];
                if (v == 1.0f) ones++;
                else if (v != 0.0f) { ok = false; break; }
            }
            if (ok && ones > 0) mode = 2;
        }
        if (mode == 0) {
            bool ok = true; int ones = 0;
            for (int i = 0; i < 256; i++) {
                int v = ii[i];
                if (v == 1) ones++;
                else if (v != 0) { ok = false; break; }
            }
            if (ok && ones > 0) mode = 1;
        }
        g_mask_mode = mode;
    }
}

// ---------------- Kernel 1: x fp32 -> fp16 ----------------
__global__ void convert_x_kernel(const float* __restrict__ x) {
    size_t i = ((size_t)blockIdx.x * blockDim.x + threadIdx.x) * 8;
    float4 a = *reinterpret_cast<const float4*>(x + i);
    float4 b = *reinterpret_cast<const float4*>(x + i + 4);
    __half2 h0 = __floats2half2_rn(a.x, a.y);
    __half2 h1 = __floats2half2_rn(a.z, a.w);
    __half2 h2 = __floats2half2_rn(b.x, b.y);
    __half2 h3 = __floats2half2_rn(b.z, b.w);
    uint4 o;
    o.x = *reinterpret_cast<uint32_t*>(&h0);
    o.y = *reinterpret_cast<uint32_t*>(&h1);
    o.z = *reinterpret_cast<uint32_t*>(&h2);
    o.w = *reinterpret_cast<uint32_t*>(&h3);
    *reinterpret_cast<uint4*>(g_xf16 + i) = o;
}

// ---------------- Kernel 2: int4 block dequant -> fp16 [OUT][IN] ----------------
__global__ void dequant_w_kernel(const int* __restrict__ packed,
                                 const void* __restrict__ scale,
                                 const void* __restrict__ mask) {
    int nb = blockIdx.x * blockDim.x + threadIdx.x;

    float sc;
    int smode = g_scale_mode;
    if (smode == 0)      sc = __half2float(((const __half*)scale)[nb]);
    else if (smode == 1) sc = __bfloat162float(((const __nv_bfloat16*)scale)[nb]);
    else                 sc = ((const float*)scale)[nb];

    bool mk;
    int mmode = g_mask_mode;
    if (mmode == 0)      mk = ((const unsigned char*)mask)[nb] != 0;
    else if (mmode == 1) mk = ((const int*)mask)[nb] != 0;
    else                 mk = ((const float*)mask)[nb] != 0.0f;

    float se = sc * (mk ? 1.0f : 0.5f);
    const int4* p = reinterpret_cast<const int4*>(packed) + (size_t)nb * 4;
    uint4* dst = reinterpret_cast<uint4*>(g_wf16 + (size_t)nb * G_BLK);
#pragma unroll
    for (int g = 0; g < 4; g++) {
        int4 v = p[g];
        int vv[4] = {v.x, v.y, v.z, v.w};
        uint32_t res[4];
#pragma unroll
        for (int j = 0; j < 4; j++) {
            int b = vv[j];
            float lo = (float)((b & 0xF) - 8) * se;
            float hi = (float)(((b >> 4) & 0xF) - 8) * se;
            __half2 h = __floats2half2_rn(lo, hi);
            res[j] = *reinterpret_cast<uint32_t*>(&h);
        }
        dst[g] = make_uint4(res[0], res[1], res[2], res[3]);
    }
}

// ---------------- Kernel 3: HMMA fp16 GEMM 128x128x64, 3 stages, 2 CTAs/SM ----------------
#define STAGE_BYTES (BLK_M * 128 + BLK_N * 128)       // 16K A + 16K B = 32K
#define SMEM_TOTAL  (STAGES * STAGE_BYTES)            // 96K -> 2 CTAs/SM

__global__ void __launch_bounds__(GEMM_THREADS, 2)
gemm_kernel(const float* __restrict__ bias, float* __restrict__ out) {
    extern __shared__ __align__(1024) char smem[];
    const uint32_t sb = smem_u32(smem);
    const int tid = threadIdx.x;
    const int wid = tid >> 5;
    const int lid = tid & 31;

    // CTA swizzle: groups of 8 m-tiles x all 32 n-tiles -> B stays L2-resident
    const int bid = blockIdx.x;
    const int group = bid >> 8;           // 256 CTAs per group
    const int rem = bid & 255;
    const int mt = (group << 3) + (rem & 7);
    const int nt = rem >> 3;              // 0..31
    const int m_base = mt * BLK_M;
    const int n_base = nt * BLK_N;

    // producer addressing: each thread copies 4 A rows + 4 B rows (16B chunk each)
    const int ch = tid & 7;               // 16B chunk within 128B row
    const int row0 = tid >> 3;            // 0..31
    const __half* aCol = g_xf16 + (size_t)m_base * K_TOT + (size_t)ch * 8;
    const __half* bCol = g_wf16 + (size_t)n_base * K_TOT + (size_t)ch * 8;

    auto issue_stage = [&](int it) {
        const int s = it % STAGES;
        const uint32_t stA = sb + s * STAGE_BYTES;
        const uint32_t stB = stA + BLK_M * 128;
        const __half* aSrc = aCol + (size_t)it * BLK_K;
        const __half* bSrc = bCol + (size_t)it * BLK_K;
#pragma unroll
        for (int r = 0; r < 4; r++) {
            int row = row0 + (r << 5);
            uint32_t off = row * 128 + ch * 16;
            cp16(stA + sw128(off), aSrc + (size_t)row * K_TOT);
        }
#pragma unroll
        for (int r = 0; r < 4; r++) {
            int row = row0 + (r << 5);
            uint32_t off = row * 128 + ch * 16;
            cp16(stB + sw128(off), bSrc + (size_t)row * K_TOT);
        }
        cp_commit();
    };

    // prologue: fill STAGES-1 stages
#pragma unroll
    for (int it = 0; it < STAGES - 1; it++) issue_stage(it);

    // warp tiling: 4 warps along M, 2 along N; warp tile 32x64
    const int wm = wid >> 1;              // 0..3
    const int wn = wid & 1;               // 0..1
    float acc[2][8][4];                   // [m16][n8][frag]
#pragma unroll
    for (int i = 0; i < 2; i++)
#pragma unroll
        for (int j = 0; j < 8; j++)
#pragma unroll
            for (int k = 0; k < 4; k++) acc[i][j][k] = 0.f;

    const int lrow = lid & 15;
    const int lcol = (lid >> 4) << 3;

#pragma unroll 1
    for (int it = 0; it < K_ITERS; it++) {
        cp_wait<STAGES - 2>();
        __syncthreads();
        // issue next stage into slot (it-1)%S; ordered vs last iter's reads by the sync
        if (it + STAGES - 1 < K_ITERS) issue_stage(it + STAGES - 1);

        const int s = it % STAGES;
        const uint32_t stA = sb + s * STAGE_BYTES;
        const uint32_t stB = stA + BLK_M * 128;

#pragma unroll
        for (int ks = 0; ks < 4; ks++) {          // 4 x k16 per BLK_K=64
            const int kh = ks * 16 + lcol;
            uint32_t a[2][4], b[4][4];
#pragma unroll
            for (int mi = 0; mi < 2; mi++) {
                int row = wm * 32 + mi * 16 + lrow;
                ldmatrix_x4(a[mi], stA + sw128(row * 128 + kh * 2));
            }
#pragma unroll
            for (int ni = 0; ni < 4; ni++) {
                int row = wn * 64 + ni * 16 + lrow;
                ldmatrix_x4(b[ni], stB + sw128(row * 128 + kh * 2));
            }
#pragma unroll
            for (int mi = 0; mi < 2; mi++)
#pragma unroll
                for (int ni = 0; ni < 4; ni++) {
                    mma16816(acc[mi][ni * 2 + 0], a[mi], b[ni][0], b[ni][2]);
                    mma16816(acc[mi][ni * 2 + 1], a[mi], b[ni][1], b[ni][3]);
                }
        }
    }

    // ---------------- epilogue: fused bias, fp32 out ----------------
    const int qid = lid >> 2;
    const int qtid = lid & 3;
#pragma unroll
    for (int mi = 0; mi < 2; mi++) {
#pragma unroll
        for (int ni = 0; ni < 8; ni++) {
            int col = n_base + wn * 64 + ni * 8 + qtid * 2;
            float2 bv = *reinterpret_cast<const float2*>(bias + col);
            int r0 = m_base + wm * 32 + mi * 16 + qid;
            float2 o0 = make_float2(acc[mi][ni][0] + bv.x, acc[mi][ni][1] + bv.y);
            float2 o1 = make_float2(acc[mi][ni][2] + bv.x, acc[mi][ni][3] + bv.y);
            *reinterpret_cast<float2*>(out + (size_t)r0 * N_TOT + col) = o0;
            *reinterpret_cast<float2*>(out + (size_t)(r0 + 8) * N_TOT + col) = o1;
        }
    }
}

// ---------------- host ----------------
extern "C" void kernel_launch(void* const* d_in, const int* in_sizes, int n_in,
                              void* d_out, int out_size) {
    (void)in_sizes; (void)n_in; (void)out_size;
    const float* x          = (const float*)d_in[0];
    const int* wpacked      = (const int*)d_in[1];
    const void* wscale      = d_in[2];
    const void* wm          = d_in[3];
    const float* bias       = (const float*)d_in[4];
    float* out              = (float*)d_out;

    cudaFuncSetAttribute(gemm_kernel, cudaFuncAttributeMaxDynamicSharedMemorySize, SMEM_TOTAL);

    detect_kernel<<<1, 1>>>(wscale, wm);
    convert_x_kernel<<<(size_t)M_TOT * K_TOT / (8 * 256), 256>>>(x);
    dequant_w_kernel<<<NB_BLOCKS / 256, 256>>>(wpacked, wscale, wm);
    gemm_kernel<<<(M_TOT / BLK_M) * (N_TOT / BLK_N), GEMM_THREADS, SMEM_TOTAL>>>(bias, out);
}

// round 7
// speedup vs baseline: 1.2137x; 1.0359x over previous
#include <cuda_runtime.h>
#include <cuda_fp16.h>
#include <cuda_bf16.h>
#include <cstdint>

// y[16384,4096] = x[16384,4096] @ w[4096,4096]^T + b
#define M_TOT 16384
#define N_TOT 4096
#define K_TOT 4096
#define G_BLK 32
#define NB_BLOCKS ((N_TOT * K_TOT) / G_BLK)   // 524288

#define BLK_M 128
#define BLK_N 128
#define BLK_K 64                  // halves; one 128B smem row per tile-row
#define K_ITERS (K_TOT / BLK_K)   // 64
#define STAGES 3
#define GEMM_THREADS 256          // 8 warps: 4 along M x 2 along N, warp tile 32x64

// Scratch (allocation-free rule: __device__ globals)
__device__ __half g_xf16[(size_t)M_TOT * K_TOT];   // 128 MB
__device__ __half g_wf16[(size_t)N_TOT * K_TOT];   // 32 MB
__device__ int g_scale_mode;   // 0=fp16, 1=bf16, 2=fp32
__device__ int g_mask_mode;    // 0=u8, 1=i32, 2=f32

// ---------------- helpers ----------------
__device__ __forceinline__ uint32_t smem_u32(const void* p) {
    uint32_t a;
    asm("{ .reg .u64 t; cvta.to.shared.u64 t, %1; cvt.u32.u64 %0, t; }" : "=r"(a) : "l"(p));
    return a;
}
__device__ __forceinline__ void cp16(uint32_t dst, const void* src) {
    asm volatile("cp.async.cg.shared.global [%0], [%1], 16;" :: "r"(dst), "l"(src) : "memory");
}
__device__ __forceinline__ void ldmatrix_x4(uint32_t* r, uint32_t addr) {
    asm volatile("ldmatrix.sync.aligned.m8n8.x4.shared.b16 {%0,%1,%2,%3}, [%4];"
                 : "=r"(r[0]), "=r"(r[1]), "=r"(r[2]), "=r"(r[3]) : "r"(addr));
}
__device__ __forceinline__ void mma16816(float* c, const uint32_t* a, uint32_t b0, uint32_t b1) {
    asm volatile(
        "mma.sync.aligned.m16n8k16.row.col.f32.f16.f16.f32 "
        "{%0,%1,%2,%3}, {%4,%5,%6,%7}, {%8,%9}, {%0,%1,%2,%3};"
        : "+f"(c[0]), "+f"(c[1]), "+f"(c[2]), "+f"(c[3])
        : "r"(a[0]), "r"(a[1]), "r"(a[2]), "r"(a[3]), "r"(b0), "r"(b1));
}
__device__ __forceinline__ uint32_t sw128(uint32_t off) {   // SW128 swizzle
    return off ^ ((off >> 3) & 0x70);
}

#define MBAR_INIT(addr, cnt) \
    asm volatile("mbarrier.init.shared.b64 [%0], %1;" :: "r"(addr), "r"(cnt) : "memory")
#define MBAR_ARRIVE(addr) \
    asm volatile("mbarrier.arrive.shared.b64 _, [%0];" :: "r"(addr) : "memory")
#define CPASYNC_ARRIVE_NOINC(addr) \
    asm volatile("cp.async.mbarrier.arrive.noinc.shared::cta.b64 [%0];" :: "r"(addr) : "memory")

#define MBAR_WAIT(mbar_addr, phase_parity) do {                                          \
    uint32_t _mbar = (uint32_t)(mbar_addr);                                              \
    uint32_t _parity = (uint32_t)(phase_parity);                                         \
    uint32_t _done;                                                                      \
    asm volatile(                                                                        \
        "{\n\t.reg .pred p;\n\t"                                                         \
        "mbarrier.try_wait.parity.acquire.cta.shared::cta.b64 p, [%1], %2;\n\t"          \
        "selp.b32 %0, 1, 0, p;\n\t}"                                                     \
        : "=r"(_done) : "r"(_mbar), "r"(_parity) : "memory");                            \
    if (!_done) {                                                                        \
        asm volatile(                                                                    \
            "{\n\t.reg .pred P1;\n\t"                                                    \
            "WAIT_LOOP_%=:\n\t"                                                          \
            "mbarrier.try_wait.parity.acquire.cta.shared::cta.b64 P1, [%0], %1, 0x989680;\n\t" \
            "@P1 bra.uni WAIT_DONE_%=;\n\t"                                              \
            "bra.uni WAIT_LOOP_%=;\n\t"                                                  \
            "WAIT_DONE_%=:\n\t}"                                                         \
            :: "r"(_mbar), "r"(_parity) : "memory");                                     \
    }                                                                                    \
} while (0)

// ---------------- Kernel 0: detect input encodings ----------------
__global__ void detect_kernel(const void* scale_raw, const void* mask_raw) {
    if (threadIdx.x != 0 || blockIdx.x != 0) return;
    {
        const __half* h = (const __half*)scale_raw;
        const __nv_bfloat16* bf = (const __nv_bfloat16*)scale_raw;
        int mode = 2;
        {
            bool ok = true; float s = 0.f, mx = 0.f;
            for (int i = 0; i < 256; i++) {
                float v = fabsf(__half2float(h[i]));
                if (!(v == v) || v > 1e30f) { ok = false; break; }
                s += v; if (v > mx) mx = v;
            }
            if (ok && mx < 0.05f && s > 256 * 0.005f && s < 256 * 0.015f) mode = 0;
        }
        if (mode == 2) {
            bool ok = true; float s = 0.f, mx = 0.f;
            for (int i = 0; i < 256; i++) {
                float v = fabsf(__bfloat162float(bf[i]));
                if (!(v == v) || v > 1e30f) { ok = false; break; }
                s += v; if (v > mx) mx = v;
            }
            if (ok && mx < 0.05f && s > 256 * 0.005f && s < 256 * 0.015f) mode = 1;
        }
        g_scale_mode = mode;
    }
    {
        const float* f = (const float*)mask_raw;
        const int* ii = (const int*)mask_raw;
        int mode = 0;
        {
            bool ok = true; int ones = 0;
            for (int i = 0; i < 256; i++) {
                float v = f[i];
                if (v == 1.0f) ones++;
                else if (v != 0.0f) { ok = false; break; }
            }
            if (ok && ones > 0) mode = 2;
        }
        if (mode == 0) {
            bool ok = true; int ones = 0;
            for (int i = 0; i < 256; i++) {
                int v = ii[i];
                if (v == 1) ones++;
                else if (v != 0) { ok = false; break; }
            }
            if (ok && ones > 0) mode = 1;
        }
        g_mask_mode = mode;
    }
}

// ---------------- Kernel 1: x fp32 -> fp16 ----------------
__global__ void convert_x_kernel(const float* __restrict__ x) {
    size_t i = ((size_t)blockIdx.x * blockDim.x + threadIdx.x) * 8;
    float4 a = *reinterpret_cast<const float4*>(x + i);
    float4 b = *reinterpret_cast<const float4*>(x + i + 4);
    __half2 h0 = __floats2half2_rn(a.x, a.y);
    __half2 h1 = __floats2half2_rn(a.z, a.w);
    __half2 h2 = __floats2half2_rn(b.x, b.y);
    __half2 h3 = __floats2half2_rn(b.z, b.w);
    uint4 o;
    o.x = *reinterpret_cast<uint32_t*>(&h0);
    o.y = *reinterpret_cast<uint32_t*>(&h1);
    o.z = *reinterpret_cast<uint32_t*>(&h2);
    o.w = *reinterpret_cast<uint32_t*>(&h3);
    *reinterpret_cast<uint4*>(g_xf16 + i) = o;
}

// ---------------- Kernel 2: int4 block dequant -> fp16 [OUT][IN] ----------------
__global__ void dequant_w_kernel(const int* __restrict__ packed,
                                 const void* __restrict__ scale,
                                 const void* __restrict__ mask) {
    int nb = blockIdx.x * blockDim.x + threadIdx.x;

    float sc;
    int smode = g_scale_mode;
    if (smode == 0)      sc = __half2float(((const __half*)scale)[nb]);
    else if (smode == 1) sc = __bfloat162float(((const __nv_bfloat16*)scale)[nb]);
    else                 sc = ((const float*)scale)[nb];

    bool mk;
    int mmode = g_mask_mode;
    if (mmode == 0)      mk = ((const unsigned char*)mask)[nb] != 0;
    else if (mmode == 1) mk = ((const int*)mask)[nb] != 0;
    else                 mk = ((const float*)mask)[nb] != 0.0f;

    float se = sc * (mk ? 1.0f : 0.5f);
    const int4* p = reinterpret_cast<const int4*>(packed) + (size_t)nb * 4;
    uint4* dst = reinterpret_cast<uint4*>(g_wf16 + (size_t)nb * G_BLK);
#pragma unroll
    for (int g = 0; g < 4; g++) {
        int4 v = p[g];
        int vv[4] = {v.x, v.y, v.z, v.w};
        uint32_t res[4];
#pragma unroll
        for (int j = 0; j < 4; j++) {
            int b = vv[j];
            float lo = (float)((b & 0xF) - 8) * se;
            float hi = (float)(((b >> 4) & 0xF) - 8) * se;
            __half2 h = __floats2half2_rn(lo, hi);
            res[j] = *reinterpret_cast<uint32_t*>(&h);
        }
        dst[g] = make_uint4(res[0], res[1], res[2], res[3]);
    }
}

// ---------------- Kernel 3: HMMA GEMM 128x128x64, mbarrier pipeline, 2 CTAs/SM ------
// SMEM: [0..STAGES*16) barriers (full,empty per stage), data at 1024
#define SM_FULL(s)  ((s) * 16)
#define SM_EMPTY(s) ((s) * 16 + 8)
#define SM_STAGE0   1024
#define STAGE_BYTES (BLK_M * 128 + BLK_N * 128)       // 32K
#define SMEM_TOTAL  (SM_STAGE0 + STAGES * STAGE_BYTES) // 99328 -> 2 CTAs/SM

__global__ void __launch_bounds__(GEMM_THREADS, 2)
gemm_kernel(const float* __restrict__ bias, float* __restrict__ out) {
    extern __shared__ __align__(1024) char smem[];
    const uint32_t sb = smem_u32(smem);
    const int tid = threadIdx.x;
    const int wid = tid >> 5;
    const int lid = tid & 31;

    // CTA swizzle: groups of 8 m-tiles x all 32 n-tiles -> B stays L2-resident
    const int bid = blockIdx.x;
    const int group = bid >> 8;           // 256 CTAs per group
    const int rem = bid & 255;
    const int mt = (group << 3) + (rem & 7);
    const int nt = rem >> 3;              // 0..31
    const int m_base = mt * BLK_M;
    const int n_base = nt * BLK_N;

    if (tid == 0) {
#pragma unroll
        for (int s = 0; s < STAGES; s++) {
            MBAR_INIT(sb + SM_FULL(s), GEMM_THREADS);  // cp-arrive per thread
            MBAR_INIT(sb + SM_EMPTY(s), 8);            // one arrive per warp
        }
    }
    __syncthreads();

    // producer addressing: each thread copies 4 A rows + 4 B rows (16B chunk each)
    const int ch = tid & 7;               // 16B chunk within 128B row
    const int row0 = tid >> 3;            // 0..31
    const __half* aCol = g_xf16 + (size_t)m_base * K_TOT + (size_t)ch * 8;
    const __half* bCol = g_wf16 + (size_t)n_base * K_TOT + (size_t)ch * 8;

    auto issue_stage = [&](int it) {
        const int s = it % STAGES;
        const uint32_t stA = sb + SM_STAGE0 + s * STAGE_BYTES;
        const uint32_t stB = stA + BLK_M * 128;
        const __half* aSrc = aCol + (size_t)it * BLK_K;
        const __half* bSrc = bCol + (size_t)it * BLK_K;
#pragma unroll
        for (int r = 0; r < 4; r++) {
            int row = row0 + (r << 5);
            uint32_t off = row * 128 + ch * 16;
            cp16(stA + sw128(off), aSrc + (size_t)row * K_TOT);
        }
#pragma unroll
        for (int r = 0; r < 4; r++) {
            int row = row0 + (r << 5);
            uint32_t off = row * 128 + ch * 16;
            cp16(stB + sw128(off), bSrc + (size_t)row * K_TOT);
        }
        CPASYNC_ARRIVE_NOINC(sb + SM_FULL(s));
    };

    // prologue: fill STAGES-1 stages (slots fresh, no empty-wait)
#pragma unroll
    for (int it = 0; it < STAGES - 1; it++) issue_stage(it);

    // warp tiling: 4 warps along M, 2 along N; warp tile 32x64
    const int wm = wid >> 1;              // 0..3
    const int wn = wid & 1;               // 0..1
    float acc[2][8][4];                   // [m16][n8][frag]
#pragma unroll
    for (int i = 0; i < 2; i++)
#pragma unroll
        for (int j = 0; j < 8; j++)
#pragma unroll
            for (int k = 0; k < 4; k++) acc[i][j][k] = 0.f;

    const int lrow = lid & 15;
    const int lcol = (lid >> 4) << 3;

#pragma unroll 1
    for (int it = 0; it < K_ITERS; it++) {
        // ---- produce stage p = it + STAGES-1 into slot p%STAGES ----
        const int p = it + STAGES - 1;
        if (p < K_ITERS) {
            const int ps = p % STAGES;
            if (p >= STAGES) MBAR_WAIT(sb + SM_EMPTY(ps), ((p / STAGES) - 1) & 1);
            issue_stage(p);
        }

        // ---- consume stage it ----
        const int s = it % STAGES;
        MBAR_WAIT(sb + SM_FULL(s), (it / STAGES) & 1);
        const uint32_t stA = sb + SM_STAGE0 + s * STAGE_BYTES;
        const uint32_t stB = stA + BLK_M * 128;

#pragma unroll
        for (int ks = 0; ks < 4; ks++) {          // 4 x k16 per BLK_K=64
            const int kh = ks * 16 + lcol;
            uint32_t a[2][4], b[4][4];
#pragma unroll
            for (int mi = 0; mi < 2; mi++) {
                int row = wm * 32 + mi * 16 + lrow;
                ldmatrix_x4(a[mi], stA + sw128(row * 128 + kh * 2));
            }
#pragma unroll
            for (int ni = 0; ni < 4; ni++) {
                int row = wn * 64 + ni * 16 + lrow;
                ldmatrix_x4(b[ni], stB + sw128(row * 128 + kh * 2));
            }
#pragma unroll
            for (int mi = 0; mi < 2; mi++)
#pragma unroll
                for (int ni = 0; ni < 4; ni++) {
                    mma16816(acc[mi][ni * 2 + 0], a[mi], b[ni][0], b[ni][2]);
                    mma16816(acc[mi][ni * 2 + 1], a[mi], b[ni][1], b[ni][3]);
                }
        }
        // MMAs consumed the regs -> LDSM smem reads complete -> safe to recycle slot
        if (lid == 0) MBAR_ARRIVE(sb + SM_EMPTY(s));
    }

    // ---------------- epilogue: fused bias, fp32 out ----------------
    const int qid = lid >> 2;
    const int qtid = lid & 3;
#pragma unroll
    for (int mi = 0; mi < 2; mi++) {
#pragma unroll
        for (int ni = 0; ni < 8; ni++) {
            int col = n_base + wn * 64 + ni * 8 + qtid * 2;
            float2 bv = *reinterpret_cast<const float2*>(bias + col);
            int r0 = m_base + wm * 32 + mi * 16 + qid;
            float2 o0 = make_float2(acc[mi][ni][0] + bv.x, acc[mi][ni][1] + bv.y);
            float2 o1 = make_float2(acc[mi][ni][2] + bv.x, acc[mi][ni][3] + bv.y);
            *reinterpret_cast<float2*>(out + (size_t)r0 * N_TOT + col) = o0;
            *reinterpret_cast<float2*>(out + (size_t)(r0 + 8) * N_TOT + col) = o1;
        }
    }
}

// ---------------- host ----------------
extern "C" void kernel_launch(void* const* d_in, const int* in_sizes, int n_in,
                              void* d_out, int out_size) {
    (void)in_sizes; (void)n_in; (void)out_size;
    const float* x          = (const float*)d_in[0];
    const int* wpacked      = (const int*)d_in[1];
    const void* wscale      = d_in[2];
    const void* wm          = d_in[3];
    const float* bias       = (const float*)d_in[4];
    float* out              = (float*)d_out;

    cudaFuncSetAttribute(gemm_kernel, cudaFuncAttributeMaxDynamicSharedMemorySize, SMEM_TOTAL);

    detect_kernel<<<1, 1>>>(wscale, wm);
    convert_x_kernel<<<(size_t)M_TOT * K_TOT / (8 * 256), 256>>>(x);
    dequant_w_kernel<<<NB_BLOCKS / 256, 256>>>(wpacked, wscale, wm);
    gemm_kernel<<<(M_TOT / BLK_M) * (N_TOT / BLK_N), GEMM_THREADS, SMEM_TOTAL>>>(bias, out);
}